// round 15
// baseline (speedup 1.0000x reference)
#include <cuda_runtime.h>
#include <cuda_fp16.h>
#include <cstdint>

// GraphConvolution: out[b] = adj[b] @ (x[b] @ W) + bias
// B=8, N=2048, F=128.
// Phase 1: 3-term FP16 mma.sync (fp32-accurate support), epilogue quantizes to
//          two s8 planes stored TRANSPOSED [b][f][n] (k-major B for phase 2).
// Phase 2: 3-term INT8 mma.sync m16n8k32 (s32 accum, exact):
//          adj = a_hi/127 + a_lo/32512 (on-the-fly quant in staging),
//          support = b_hi/32 + b_lo/8192. Cross terms share one accumulator
//          (equal scales). 512 thr / 16 warps / 32x32 warp tiles, k32 chunks,
//          triple buffer, 1 sync/chunk, ldmatrix fragments.

constexpr int BB = 8;
constexpr int NN = 2048;
constexpr int FF = 128;

// transposed s8 support planes: [b][f][n] (2 MB each)
__device__ int8_t g_q_hi[BB * FF * NN];
__device__ int8_t g_q_lo[BB * FF * NN];

// ---------------- common helpers ----------------
__device__ __forceinline__ unsigned s2u(const void* p) {
    return (unsigned)__cvta_generic_to_shared(p);
}
__device__ __forceinline__ void cp16(void* dst, const void* src) {
    asm volatile("cp.async.cg.shared.global [%0], [%1], 16;" :: "r"(s2u(dst)), "l"(src));
}
__device__ __forceinline__ void cpcommit() { asm volatile("cp.async.commit_group;"); }
__device__ __forceinline__ void cpwait1()  { asm volatile("cp.async.wait_group 1;"); }
__device__ __forceinline__ void cpwait0()  { asm volatile("cp.async.wait_group 0;"); }

__device__ __forceinline__ void ldsm_x4(unsigned r[4], unsigned a) {
    asm volatile("ldmatrix.sync.aligned.m8n8.x4.shared.b16 {%0,%1,%2,%3}, [%4];"
                 : "=r"(r[0]), "=r"(r[1]), "=r"(r[2]), "=r"(r[3]) : "r"(a));
}
__device__ __forceinline__ void mma_f16(float c[4], const unsigned a[4],
                                        unsigned b0, unsigned b1) {
    asm volatile(
        "mma.sync.aligned.m16n8k16.row.col.f32.f16.f16.f32 "
        "{%0,%1,%2,%3}, {%4,%5,%6,%7}, {%8,%9}, {%0,%1,%2,%3};"
        : "+f"(c[0]), "+f"(c[1]), "+f"(c[2]), "+f"(c[3])
        : "r"(a[0]), "r"(a[1]), "r"(a[2]), "r"(a[3]), "r"(b0), "r"(b1));
}
__device__ __forceinline__ void mma_s8(int c[4], const unsigned a[4],
                                       unsigned b0, unsigned b1) {
    asm volatile(
        "mma.sync.aligned.m16n8k32.row.col.s32.s8.s8.s32 "
        "{%0,%1,%2,%3}, {%4,%5,%6,%7}, {%8,%9}, {%0,%1,%2,%3};"
        : "+r"(c[0]), "+r"(c[1]), "+r"(c[2]), "+r"(c[3])
        : "r"(a[0]), "r"(a[1]), "r"(a[2]), "r"(a[3]), "r"(b0), "r"(b1));
}
__device__ __forceinline__ void split_h2(float x, float y, __half2& h, __half2& l) {
    h = __floats2half2_rn(x, y);
    float lx = x - __half2float(__low2half(h));
    float ly = y - __half2float(__high2half(h));
    l = __floats2half2_rn(lx, ly);
}
__device__ __forceinline__ unsigned h2u(__half2 h) {
    return *reinterpret_cast<unsigned*>(&h);
}
__device__ __forceinline__ unsigned pack4(int b0, int b1, int b2, int b3) {
    return (b0 & 255) | ((b1 & 255) << 8) | ((b2 & 255) << 16) | (b3 << 24);
}
// support quantization: s = h/32 + l/8192 (+eps)
__device__ __forceinline__ void quant_s(float s, int& ih, int& il) {
    ih = __float2int_rn(s * 32.f);
    ih = max(-127, min(127, ih));
    float r = fmaf((float)ih, -0.03125f, s);      // exact (1/32)
    il = __float2int_rn(r * 8192.f);
    il = max(-127, min(127, il));
}

// ======================================================================
// Phase 1: support = x @ W (3-term f16 mma), 64 rows/CTA, single chunk,
//          epilogue quantizes fp32 acc -> transposed s8 planes [f][n].
// ======================================================================
constexpr int P1_BM  = 64;
constexpr int LDA_S  = 132;
constexpr int LDB_S  = 136;
constexpr int X_TILE = P1_BM * LDA_S;
constexpr int W_TILE = FF * LDB_S;
constexpr int P1_SMEM = (X_TILE + W_TILE) * 4;   // 103424 B

__global__ __launch_bounds__(256, 1)
void phase1_kernel(const float* __restrict__ x, const float* __restrict__ w)
{
    extern __shared__ float smem1[];
    float* Xs = smem1;
    float* Ws = smem1 + X_TILE;

    const int tid = threadIdx.x;
    const int mtile = blockIdx.x;            // 256 tiles over 16384 rows
    const float* A = x + (size_t)mtile * P1_BM * FF;

    const int warp = tid >> 5, lane = tid & 31;
    const int wm = (warp & 1) * 32;
    const int wn = (warp >> 1) * 32;
    const int g = lane >> 2, t = lane & 3;

#pragma unroll
    for (int i = 0; i < 8; i++) {
        int idx = tid + i * 256;
        int r = idx >> 5, c = idx & 31;
        cp16(Xs + r * LDA_S + c * 4, A + (size_t)r * FF + c * 4);
    }
#pragma unroll
    for (int i = 0; i < 16; i++) {
        int idx = tid + i * 256;
        int r = idx >> 5, c = idx & 31;
        cp16(Ws + r * LDB_S + c * 4, w + (size_t)r * FF + c * 4);
    }
    cpcommit();
    cpwait0();
    __syncthreads();

    float acc[2][4][4];
#pragma unroll
    for (int i = 0; i < 2; i++)
#pragma unroll
        for (int j = 0; j < 4; j++)
#pragma unroll
            for (int k = 0; k < 4; k++) acc[i][j][k] = 0.f;

#pragma unroll
    for (int ks = 0; ks < 8; ks++) {
        unsigned ah[2][4], al[2][4], bh[4][2], bl[4][2];
        const float* Ab = Xs + (wm + g) * LDA_S + ks * 16 + 2 * t;
#pragma unroll
        for (int mf = 0; mf < 2; mf++) {
            const float* p = Ab + mf * 16 * LDA_S;
            float2 v00 = *(const float2*)(p);
            float2 v10 = *(const float2*)(p + 8 * LDA_S);
            float2 v01 = *(const float2*)(p + 8);
            float2 v11 = *(const float2*)(p + 8 * LDA_S + 8);
            __half2 h, l;
            split_h2(v00.x, v00.y, h, l); ah[mf][0] = h2u(h); al[mf][0] = h2u(l);
            split_h2(v10.x, v10.y, h, l); ah[mf][1] = h2u(h); al[mf][1] = h2u(l);
            split_h2(v01.x, v01.y, h, l); ah[mf][2] = h2u(h); al[mf][2] = h2u(l);
            split_h2(v11.x, v11.y, h, l); ah[mf][3] = h2u(h); al[mf][3] = h2u(l);
        }
        const float* Bb = Ws + (ks * 16 + 2 * t) * LDB_S + wn + g;
#pragma unroll
        for (int nf = 0; nf < 4; nf++) {
            float w0 = Bb[nf * 8];
            float w1 = Bb[LDB_S + nf * 8];
            float w2 = Bb[8 * LDB_S + nf * 8];
            float w3 = Bb[9 * LDB_S + nf * 8];
            __half2 h, l;
            split_h2(w0, w1, h, l); bh[nf][0] = h2u(h); bl[nf][0] = h2u(l);
            split_h2(w2, w3, h, l); bh[nf][1] = h2u(h); bl[nf][1] = h2u(l);
        }
#pragma unroll
        for (int mf = 0; mf < 2; mf++)
#pragma unroll
            for (int nf = 0; nf < 4; nf++)
                mma_f16(acc[mf][nf], al[mf], bh[nf][0], bh[nf][1]);
#pragma unroll
        for (int mf = 0; mf < 2; mf++)
#pragma unroll
            for (int nf = 0; nf < 4; nf++)
                mma_f16(acc[mf][nf], ah[mf], bl[nf][0], bl[nf][1]);
#pragma unroll
        for (int mf = 0; mf < 2; mf++)
#pragma unroll
            for (int nf = 0; nf < 4; nf++)
                mma_f16(acc[mf][nf], ah[mf], bh[nf][0], bh[nf][1]);
    }

    // epilogue: quantize and store transposed s8 planes [b][f][n]
    const int rowbase = mtile * P1_BM;
#pragma unroll
    for (int mf = 0; mf < 2; mf++) {
        int gr = rowbase + wm + mf * 16 + g;     // global row
        int b = gr >> 11, n = gr & 2047;
#pragma unroll
        for (int nf = 0; nf < 4; nf++) {
            int col = wn + nf * 8 + 2 * t;
            size_t f0 = ((size_t)b * FF + col) * NN;
            size_t f1 = ((size_t)b * FF + col + 1) * NN;
            int ih, il;
            quant_s(acc[mf][nf][0], ih, il);
            g_q_hi[f0 + n] = (int8_t)ih; g_q_lo[f0 + n] = (int8_t)il;
            quant_s(acc[mf][nf][1], ih, il);
            g_q_hi[f1 + n] = (int8_t)ih; g_q_lo[f1 + n] = (int8_t)il;
            quant_s(acc[mf][nf][2], ih, il);
            g_q_hi[f0 + n + 8] = (int8_t)ih; g_q_lo[f0 + n + 8] = (int8_t)il;
            quant_s(acc[mf][nf][3], ih, il);
            g_q_hi[f1 + n + 8] = (int8_t)ih; g_q_lo[f1 + n + 8] = (int8_t)il;
        }
    }
}

// ======================================================================
// Phase 2: out[b] = adj[b] @ support[b] + bias  (3-term INT8 IMMA)
// 512 thr / 16 warps / 32x32 warp tiles / k32 chunks / triple buffer
// ======================================================================
constexpr int LD8      = 48;                  // bytes per row (32 data + 16 pad)
constexpr int PLANE8   = 128 * LD8;           // 6144 per plane
constexpr int STG8     = 2 * PLANE8;          // 12288 per stage (hi, lo)
constexpr int OFF_BIAS = 0;
constexpr int OFF_A    = 1024;
constexpr int OFF_B    = OFF_A + 3 * STG8;    // 37888
constexpr int P2_SMEM  = OFF_B + 3 * STG8;    // 74752

__global__ __launch_bounds__(512, 1)
void phase2_kernel(const float* __restrict__ adj, const float* __restrict__ bias,
                   float* __restrict__ out)
{
    extern __shared__ __align__(16) char smem[];
    const unsigned sA = s2u(smem + OFF_A);
    const unsigned sB = s2u(smem + OFF_B);
    const int tid = threadIdx.x, warp = tid >> 5, lane = tid & 31;
    const int mtile = blockIdx.x, b = blockIdx.y;

    const float* A = adj + ((size_t)b * NN + (size_t)mtile * 128) * NN;
    const int8_t* QH = g_q_hi + (size_t)b * FF * NN;
    const int8_t* QL = g_q_lo + (size_t)b * FF * NN;
    float* C = out + ((size_t)b * NN + (size_t)mtile * 128) * FF;

    if (tid < 128) ((float*)(smem + OFF_BIAS))[tid] = bias[tid];

    // staging roles (512 threads)
    const int ar = tid >> 2, aq = tid & 3;        // A: row 0..127, 8-float (32B k) quarter
    const int bf = tid >> 2, bsub = tid & 3;      // B: f 0..127, (plane, 16B seg)
    const int bpl = bsub >> 1, bseg = bsub & 1;

    // fragment geometry: 16 warps, 32(M) x 32(N) tiles
    const int g = lane >> 2, t = lane & 3;
    const int wm = (warp & 3) * 32;
    const int wn = (warp >> 2) * 32;
    // A ldsm addr: row = wm + (lane&15), koff = (lane>>4)*16
    const unsigned aoff8 = (unsigned)((wm + (lane & 15)) * LD8 + (lane >> 4) * 16);
    // B ldsm addr: f = wn + (lane&7) + ((lane>>4)&1)*8, koff = ((lane>>3)&1)*16
    const unsigned boff8 = (unsigned)((wn + (lane & 7) + ((lane >> 4) & 1) * 8) * LD8
                                      + ((lane >> 3) & 1) * 16);

    int acch[2][4][4], accx[2][4][4];
#pragma unroll
    for (int i = 0; i < 2; i++)
#pragma unroll
        for (int j = 0; j < 4; j++)
#pragma unroll
            for (int k = 0; k < 4; k++) { acch[i][j][k] = 0; accx[i][j][k] = 0; }

    auto ldgA = [&](int kc, float4 v[2]) {
        const float* p = A + (size_t)ar * NN + kc * 32 + aq * 8;
        v[0] = *(const float4*)p;
        v[1] = *(const float4*)(p + 4);
    };
    // quantize 8 adj values -> s8 hi/lo and store to smem
    auto stsA = [&](int kc, const float4 v[2]) {
        float f[8] = { v[0].x, v[0].y, v[0].z, v[0].w, v[1].x, v[1].y, v[1].z, v[1].w };
        int ih[8], il[8];
#pragma unroll
        for (int i = 0; i < 8; i++) {
            ih[i] = __float2int_rn(f[i] * 127.f);                 // [0,127]
            float r = fmaf((float)ih[i], -7.874015748e-3f, f[i]); // 1/127
            il[i] = min(__float2int_rn(r * 32512.f), 127);
        }
        uint2 H, L;
        H.x = pack4(ih[0], ih[1], ih[2], ih[3]);
        H.y = pack4(ih[4], ih[5], ih[6], ih[7]);
        L.x = pack4(il[0], il[1], il[2], il[3]);
        L.y = pack4(il[4], il[5], il[6], il[7]);
        char* d = smem + OFF_A + (kc % 3) * STG8 + ar * LD8 + aq * 8;
        *(uint2*)d = H;
        *(uint2*)(d + PLANE8) = L;
    };
    auto cpB = [&](int kc) {
        const int8_t* src = (bpl ? QL : QH) + (size_t)bf * NN + kc * 32 + bseg * 16;
        char* dst = smem + OFF_B + (kc % 3) * STG8 + bpl * PLANE8 + bf * LD8 + bseg * 16;
        cp16(dst, src);
        cpcommit();
    };

    auto mma_chunk = [&](int j) {
        const unsigned aB = sA + j * STG8;
        const unsigned bB = sB + j * STG8;
        unsigned ah[2][4], al[2][4], bh[2][4], bl[2][4];
        ldsm_x4(ah[0], aB + aoff8);
        ldsm_x4(ah[1], aB + aoff8 + 16 * LD8);
        ldsm_x4(al[0], aB + PLANE8 + aoff8);
        ldsm_x4(al[1], aB + PLANE8 + aoff8 + 16 * LD8);
        ldsm_x4(bh[0], bB + boff8);
        ldsm_x4(bh[1], bB + boff8 + 16 * LD8);
        ldsm_x4(bl[0], bB + PLANE8 + boff8);
        ldsm_x4(bl[1], bB + PLANE8 + boff8 + 16 * LD8);
        // cross terms (shared accumulator; equal scales), then main term
#pragma unroll
        for (int mf = 0; mf < 2; mf++)
#pragma unroll
            for (int q = 0; q < 2; q++)
#pragma unroll
                for (int h = 0; h < 2; h++)
                    mma_s8(accx[mf][q * 2 + h], al[mf], bh[q][h * 2], bh[q][h * 2 + 1]);
#pragma unroll
        for (int mf = 0; mf < 2; mf++)
#pragma unroll
            for (int q = 0; q < 2; q++)
#pragma unroll
                for (int h = 0; h < 2; h++)
                    mma_s8(accx[mf][q * 2 + h], ah[mf], bl[q][h * 2], bl[q][h * 2 + 1]);
#pragma unroll
        for (int mf = 0; mf < 2; mf++)
#pragma unroll
            for (int q = 0; q < 2; q++)
#pragma unroll
                for (int h = 0; h < 2; h++)
                    mma_s8(acch[mf][q * 2 + h], ah[mf], bh[q][h * 2], bh[q][h * 2 + 1]);
    };

    // prologue: chunks 0 and 1
    {
        float4 v[2];
        ldgA(0, v); stsA(0, v); cpB(0);
        ldgA(1, v); stsA(1, v); cpB(1);
    }

    for (int kc = 0; kc < 64; kc++) {
        float4 v[2];
        const bool pre = (kc + 2 < 64);
        if (pre) ldgA(kc + 2, v);                // overlap LDG with wait+MMA
        if (kc < 63) cpwait1(); else cpwait0();
        __syncthreads();
        mma_chunk(kc % 3);
        if (pre) {
            stsA(kc + 2, v);
            cpB(kc + 2);
        }
    }

    // epilogue: out = acch/(127*32) + accx/(127*32*256) + bias
    const float c1 = 1.f / 4064.f;
    const float c2 = c1 / 256.f;
    const float* bsm = (const float*)(smem + OFF_BIAS);
#pragma unroll
    for (int mf = 0; mf < 2; mf++) {
        int r0 = wm + mf * 16 + g;
#pragma unroll
        for (int nf = 0; nf < 4; nf++) {
            int col = wn + nf * 8 + 2 * t;
            float2 bz = *reinterpret_cast<const float2*>(bsm + col);
            float2 u0, u1;
            u0.x = fmaf(c1, (float)acch[mf][nf][0], fmaf(c2, (float)accx[mf][nf][0], bz.x));
            u0.y = fmaf(c1, (float)acch[mf][nf][1], fmaf(c2, (float)accx[mf][nf][1], bz.y));
            u1.x = fmaf(c1, (float)acch[mf][nf][2], fmaf(c2, (float)accx[mf][nf][2], bz.x));
            u1.y = fmaf(c1, (float)acch[mf][nf][3], fmaf(c2, (float)accx[mf][nf][3], bz.y));
            *reinterpret_cast<float2*>(C + (size_t)r0       * FF + col) = u0;
            *reinterpret_cast<float2*>(C + (size_t)(r0 + 8) * FF + col) = u1;
        }
    }
}

// ======================================================================
extern "C" void kernel_launch(void* const* d_in, const int* in_sizes, int n_in,
                              void* d_out, int out_size) {
    const float* x    = (const float*)d_in[0];   // [8, 2048, 128]
    const float* adj  = (const float*)d_in[1];   // [8, 2048, 2048]
    const float* w    = (const float*)d_in[2];   // [128, 128]
    const float* bias = (const float*)d_in[3];   // [128]
    float* out = (float*)d_out;                  // [8, 2048, 128]

    cudaFuncSetAttribute(phase1_kernel, cudaFuncAttributeMaxDynamicSharedMemorySize, P1_SMEM);
    cudaFuncSetAttribute(phase2_kernel, cudaFuncAttributeMaxDynamicSharedMemorySize, P2_SMEM);

    phase1_kernel<<<(BB * NN) / P1_BM, 256, P1_SMEM>>>(x, w);
    phase2_kernel<<<dim3(NN / 128, BB), 512, P2_SMEM>>>(adj, bias, out);
}

// round 16
// speedup vs baseline: 2.8599x; 2.8599x over previous
#include <cuda_runtime.h>
#include <cuda_fp16.h>
#include <cstdint>

// GraphConvolution: out[b] = adj[b] @ (x[b] @ W) + bias
// B=8, N=2048, F=128.
// Phase 1: 3-term FP16 mma.sync, 64 rows/CTA, single K=128 chunk; stores
//          support hi plane (f16) and SCALED lo plane b_lo' = 4096*(s - hi).
// Phase 2: 2-term FP16 mma m16n8k16: hi term with f32 accumulator,
//          lo term with F16 ACCUMULATOR (rate experiment), out = hi + lo/4096.
//          512 thr / 16 warps / 32x32 warp tiles / BK=32 / triple buffer.

constexpr int BB = 8;
constexpr int NN = 2048;
constexpr int FF = 128;

__device__ __half g_sup_hi[BB * NN * FF];
__device__ __half g_sup_lo[BB * NN * FF];   // scaled by 4096

// ---------------- common helpers ----------------
__device__ __forceinline__ unsigned s2u(const void* p) {
    return (unsigned)__cvta_generic_to_shared(p);
}
__device__ __forceinline__ void cp16(void* dst, const void* src) {
    asm volatile("cp.async.cg.shared.global [%0], [%1], 16;" :: "r"(s2u(dst)), "l"(src));
}
__device__ __forceinline__ void cpcommit() { asm volatile("cp.async.commit_group;"); }
__device__ __forceinline__ void cpwait1()  { asm volatile("cp.async.wait_group 1;"); }
__device__ __forceinline__ void cpwait0()  { asm volatile("cp.async.wait_group 0;"); }

__device__ __forceinline__ void ldsm_x4(unsigned r[4], unsigned a) {
    asm volatile("ldmatrix.sync.aligned.m8n8.x4.shared.b16 {%0,%1,%2,%3}, [%4];"
                 : "=r"(r[0]), "=r"(r[1]), "=r"(r[2]), "=r"(r[3]) : "r"(a));
}
__device__ __forceinline__ void ldsm_x4_t(unsigned r[4], unsigned a) {
    asm volatile("ldmatrix.sync.aligned.m8n8.x4.trans.shared.b16 {%0,%1,%2,%3}, [%4];"
                 : "=r"(r[0]), "=r"(r[1]), "=r"(r[2]), "=r"(r[3]) : "r"(a));
}
// f32-accumulator HMMA
__device__ __forceinline__ void mma_f16(float c[4], const unsigned a[4],
                                        unsigned b0, unsigned b1) {
    asm volatile(
        "mma.sync.aligned.m16n8k16.row.col.f32.f16.f16.f32 "
        "{%0,%1,%2,%3}, {%4,%5,%6,%7}, {%8,%9}, {%0,%1,%2,%3};"
        : "+f"(c[0]), "+f"(c[1]), "+f"(c[2]), "+f"(c[3])
        : "r"(a[0]), "r"(a[1]), "r"(a[2]), "r"(a[3]), "r"(b0), "r"(b1));
}
// f16-accumulator HMMA (rate experiment)
__device__ __forceinline__ void mma_f16h(unsigned c[2], const unsigned a[4],
                                         unsigned b0, unsigned b1) {
    asm volatile(
        "mma.sync.aligned.m16n8k16.row.col.f16.f16.f16.f16 "
        "{%0,%1}, {%2,%3,%4,%5}, {%6,%7}, {%0,%1};"
        : "+r"(c[0]), "+r"(c[1])
        : "r"(a[0]), "r"(a[1]), "r"(a[2]), "r"(a[3]), "r"(b0), "r"(b1));
}
__device__ __forceinline__ void split_h2(float x, float y, __half2& h, __half2& l) {
    h = __floats2half2_rn(x, y);
    float lx = x - __half2float(__low2half(h));
    float ly = y - __half2float(__high2half(h));
    l = __floats2half2_rn(lx, ly);
}
// output split with scaled lo (x4096)
__device__ __forceinline__ void split_h2_scaled(float x, float y, __half2& h, __half2& l) {
    h = __floats2half2_rn(x, y);
    float lx = (x - __half2float(__low2half(h))) * 4096.f;
    float ly = (y - __half2float(__high2half(h))) * 4096.f;
    l = __floats2half2_rn(lx, ly);
}
__device__ __forceinline__ unsigned h2u(__half2 h) {
    return *reinterpret_cast<unsigned*>(&h);
}

// ======================================================================
// Phase 1: support = x @ W (3-term f16 mma), 64 rows/CTA, single chunk
// ======================================================================
constexpr int P1_BM  = 64;
constexpr int LDA_S  = 132;
constexpr int LDB_S  = 136;
constexpr int X_TILE = P1_BM * LDA_S;
constexpr int W_TILE = FF * LDB_S;
constexpr int P1_SMEM = (X_TILE + W_TILE) * 4;   // 103424 B

__global__ __launch_bounds__(256, 1)
void phase1_kernel(const float* __restrict__ x, const float* __restrict__ w)
{
    extern __shared__ float smem1[];
    float* Xs = smem1;
    float* Ws = smem1 + X_TILE;

    const int tid = threadIdx.x;
    const int mtile = blockIdx.x;            // 256 tiles over 16384 rows
    const float* A = x + (size_t)mtile * P1_BM * FF;

    const int warp = tid >> 5, lane = tid & 31;
    const int wm = (warp & 1) * 32;
    const int wn = (warp >> 1) * 32;
    const int g = lane >> 2, t = lane & 3;

#pragma unroll
    for (int i = 0; i < 8; i++) {
        int idx = tid + i * 256;
        int r = idx >> 5, c = idx & 31;
        cp16(Xs + r * LDA_S + c * 4, A + (size_t)r * FF + c * 4);
    }
#pragma unroll
    for (int i = 0; i < 16; i++) {
        int idx = tid + i * 256;
        int r = idx >> 5, c = idx & 31;
        cp16(Ws + r * LDB_S + c * 4, w + (size_t)r * FF + c * 4);
    }
    cpcommit();
    cpwait0();
    __syncthreads();

    float acc[2][4][4];
#pragma unroll
    for (int i = 0; i < 2; i++)
#pragma unroll
        for (int j = 0; j < 4; j++)
#pragma unroll
            for (int k = 0; k < 4; k++) acc[i][j][k] = 0.f;

#pragma unroll
    for (int ks = 0; ks < 8; ks++) {          // K = 128, 16 per step
        unsigned ah[2][4], al[2][4], bh[4][2], bl[4][2];
        const float* Ab = Xs + (wm + g) * LDA_S + ks * 16 + 2 * t;
#pragma unroll
        for (int mf = 0; mf < 2; mf++) {
            const float* p = Ab + mf * 16 * LDA_S;
            float2 v00 = *(const float2*)(p);
            float2 v10 = *(const float2*)(p + 8 * LDA_S);
            float2 v01 = *(const float2*)(p + 8);
            float2 v11 = *(const float2*)(p + 8 * LDA_S + 8);
            __half2 h, l;
            split_h2(v00.x, v00.y, h, l); ah[mf][0] = h2u(h); al[mf][0] = h2u(l);
            split_h2(v10.x, v10.y, h, l); ah[mf][1] = h2u(h); al[mf][1] = h2u(l);
            split_h2(v01.x, v01.y, h, l); ah[mf][2] = h2u(h); al[mf][2] = h2u(l);
            split_h2(v11.x, v11.y, h, l); ah[mf][3] = h2u(h); al[mf][3] = h2u(l);
        }
        const float* Bb = Ws + (ks * 16 + 2 * t) * LDB_S + wn + g;
#pragma unroll
        for (int nf = 0; nf < 4; nf++) {
            float w0 = Bb[nf * 8];
            float w1 = Bb[LDB_S + nf * 8];
            float w2 = Bb[8 * LDB_S + nf * 8];
            float w3 = Bb[9 * LDB_S + nf * 8];
            __half2 h, l;
            split_h2(w0, w1, h, l); bh[nf][0] = h2u(h); bl[nf][0] = h2u(l);
            split_h2(w2, w3, h, l); bh[nf][1] = h2u(h); bl[nf][1] = h2u(l);
        }
#pragma unroll
        for (int mf = 0; mf < 2; mf++)
#pragma unroll
            for (int nf = 0; nf < 4; nf++)
                mma_f16(acc[mf][nf], al[mf], bh[nf][0], bh[nf][1]);
#pragma unroll
        for (int mf = 0; mf < 2; mf++)
#pragma unroll
            for (int nf = 0; nf < 4; nf++)
                mma_f16(acc[mf][nf], ah[mf], bl[nf][0], bl[nf][1]);
#pragma unroll
        for (int mf = 0; mf < 2; mf++)
#pragma unroll
            for (int nf = 0; nf < 4; nf++)
                mma_f16(acc[mf][nf], ah[mf], bh[nf][0], bh[nf][1]);
    }

    // store hi plane + scaled lo plane, [row][f]
    const int rowbase = mtile * P1_BM;
#pragma unroll
    for (int mf = 0; mf < 2; mf++) {
        int r0 = rowbase + wm + mf * 16 + g;
#pragma unroll
        for (int nf = 0; nf < 4; nf++) {
            int col = wn + nf * 8 + 2 * t;
            __half2 h, l;
            split_h2_scaled(acc[mf][nf][0], acc[mf][nf][1], h, l);
            *(__half2*)(g_sup_hi + (size_t)r0 * FF + col) = h;
            *(__half2*)(g_sup_lo + (size_t)r0 * FF + col) = l;
            split_h2_scaled(acc[mf][nf][2], acc[mf][nf][3], h, l);
            *(__half2*)(g_sup_hi + (size_t)(r0 + 8) * FF + col) = h;
            *(__half2*)(g_sup_lo + (size_t)(r0 + 8) * FF + col) = l;
        }
    }
}

// ======================================================================
// Phase 2: out[b] = adj[b] @ support[b] + bias
// hi term f32-acc, lo term f16-acc (scaled x4096).
// 512 thr / 16 warps / 32x32 warp tiles / BK=32 / triple buffer / 1 sync
// ======================================================================
constexpr int LDA_H    = 40;                 // halves per A row (32 + 8 pad)
constexpr int A_TILE_B = 128 * LDA_H * 2;    // 10240
constexpr int LDB_B    = 272;                // bytes per B row (256 + 16 pad)
constexpr int B_PLANE  = 32 * LDB_B;         // 8704
constexpr int B_STG_B  = 2 * B_PLANE;        // 17408 (hi, lo)
constexpr int OFF_BIAS = 0;
constexpr int OFF_A    = 1024;
constexpr int OFF_B    = OFF_A + 3 * A_TILE_B;        // 31744
constexpr int P2_SMEM  = OFF_B + 3 * B_STG_B;         // 83968

__global__ __launch_bounds__(512, 1)
void phase2_kernel(const float* __restrict__ adj, const float* __restrict__ bias,
                   float* __restrict__ out)
{
    extern __shared__ __align__(16) char smem[];
    const unsigned sA = s2u(smem + OFF_A);
    const unsigned sB = s2u(smem + OFF_B);
    const int tid = threadIdx.x, warp = tid >> 5, lane = tid & 31;
    const int mtile = blockIdx.x, b = blockIdx.y;

    const float* A = adj + ((size_t)b * NN + (size_t)mtile * 128) * NN;
    const __half* BH = g_sup_hi + (size_t)b * NN * FF;
    const __half* BL = g_sup_lo + (size_t)b * NN * FF;
    float* C = out + ((size_t)b * NN + (size_t)mtile * 128) * FF;

    if (tid < 128) ((float*)(smem + OFF_BIAS))[tid] = bias[tid];

    // staging roles (512 threads)
    const int ar = tid >> 2, aq = tid & 3;        // A: row 0..127, 8-float quarter
    const int br = tid >> 4, bs = tid & 15;       // B: row 0..31, 16B segment

    // fragment geometry: 16 warps, 32(M) x 32(N) tiles
    const int g = lane >> 2, t = lane & 3;
    const int wm = (warp & 3) * 32;
    const int wn = (warp >> 2) * 32;
    const unsigned aoff = (unsigned)((wm + (lane & 7) + ((lane >> 3) & 1) * 8) * (LDA_H * 2)
                                     + (lane >> 4) * 16);
    const unsigned boff = (unsigned)(((lane & 7) + ((lane >> 3) & 1) * 8) * LDB_B
                                     + (wn + (lane >> 4) * 8) * 2);

    float    acch[2][4][4];
    unsigned accl[2][4][2];                  // f16x2 accumulators for lo term
#pragma unroll
    for (int i = 0; i < 2; i++)
#pragma unroll
        for (int j = 0; j < 4; j++) {
#pragma unroll
            for (int k = 0; k < 4; k++) acch[i][j][k] = 0.f;
            accl[i][j][0] = 0u; accl[i][j][1] = 0u;
        }

    auto ldgA = [&](int kc, float4& v0, float4& v1) {
        const float* p = A + (size_t)ar * NN + kc * 32 + aq * 8;
        v0 = *(const float4*)p;
        v1 = *(const float4*)(p + 4);
    };
    auto stsA = [&](int kc, float4 v0, float4 v1) {
        __half2 p0 = __floats2half2_rn(v0.x, v0.y);
        __half2 p1 = __floats2half2_rn(v0.z, v0.w);
        __half2 p2 = __floats2half2_rn(v1.x, v1.y);
        __half2 p3 = __floats2half2_rn(v1.z, v1.w);
        uint4 u;
        u.x = *(unsigned*)&p0; u.y = *(unsigned*)&p1;
        u.z = *(unsigned*)&p2; u.w = *(unsigned*)&p3;
        *(uint4*)(smem + OFF_A + (kc % 3) * A_TILE_B + ar * (LDA_H * 2) + aq * 16) = u;
    };
    auto cpB = [&](int kc) {
        char* dst = smem + OFF_B + (kc % 3) * B_STG_B + br * LDB_B + bs * 16;
        const __half* sh = BH + (size_t)(kc * 32 + br) * FF + bs * 8;
        const __half* sl = BL + (size_t)(kc * 32 + br) * FF + bs * 8;
        cp16(dst, sh);
        cp16(dst + B_PLANE, sl);
        cpcommit();
    };

    auto mma_chunk = [&](int j) {
        const unsigned aB = sA + j * A_TILE_B;
        const unsigned bB = sB + j * B_STG_B;
#pragma unroll
        for (int ks = 0; ks < 2; ks++) {
            unsigned af[2][4];
            ldsm_x4(af[0], aB + aoff + ks * 32);
            ldsm_x4(af[1], aB + aoff + 16 * (LDA_H * 2) + ks * 32);
            unsigned bh[2][4], bl[2][4];
            const unsigned bks = bB + boff + ks * 16 * LDB_B;
            ldsm_x4_t(bl[0], bks + B_PLANE);
            ldsm_x4_t(bl[1], bks + B_PLANE + 32);
            ldsm_x4_t(bh[0], bks);
            ldsm_x4_t(bh[1], bks + 32);
            // lo term: f16 accumulator (rate experiment)
#pragma unroll
            for (int mf = 0; mf < 2; mf++)
#pragma unroll
                for (int np = 0; np < 2; np++)
#pragma unroll
                    for (int p = 0; p < 2; p++)
                        mma_f16h(accl[mf][np * 2 + p], af[mf],
                                 bl[np][p * 2], bl[np][p * 2 + 1]);
            // hi term: f32 accumulator
#pragma unroll
            for (int mf = 0; mf < 2; mf++)
#pragma unroll
                for (int np = 0; np < 2; np++)
#pragma unroll
                    for (int p = 0; p < 2; p++)
                        mma_f16(acch[mf][np * 2 + p], af[mf],
                                bh[np][p * 2], bh[np][p * 2 + 1]);
        }
    };

    // prologue: chunks 0 and 1
    {
        float4 v0, v1;
        ldgA(0, v0, v1); stsA(0, v0, v1); cpB(0);
        ldgA(1, v0, v1); stsA(1, v0, v1); cpB(1);
    }

    for (int kc = 0; kc < 64; kc++) {
        float4 v0, v1;
        const bool pre = (kc + 2 < 64);
        if (pre) ldgA(kc + 2, v0, v1);           // overlap LDG with wait+MMA
        if (kc < 63) cpwait1(); else cpwait0();
        __syncthreads();
        mma_chunk(kc % 3);
        if (pre) {
            stsA(kc + 2, v0, v1);
            cpB(kc + 2);
        }
    }

    // epilogue: out = acch + accl/4096 + bias
    const float inv = 1.f / 4096.f;
    const float* bsm = (const float*)(smem + OFF_BIAS);
#pragma unroll
    for (int mf = 0; mf < 2; mf++) {
        int r0 = wm + mf * 16 + g;
#pragma unroll
        for (int nf = 0; nf < 4; nf++) {
            int col = wn + nf * 8 + 2 * t;
            float2 bz = *reinterpret_cast<const float2*>(bsm + col);
            float2 lo0 = __half22float2(*reinterpret_cast<__half2*>(&accl[mf][nf][0]));
            float2 lo1 = __half22float2(*reinterpret_cast<__half2*>(&accl[mf][nf][1]));
            float2 u0, u1;
            u0.x = acch[mf][nf][0] + lo0.x * inv + bz.x;
            u0.y = acch[mf][nf][1] + lo0.y * inv + bz.y;
            u1.x = acch[mf][nf][2] + lo1.x * inv + bz.x;
            u1.y = acch[mf][nf][3] + lo1.y * inv + bz.y;
            *reinterpret_cast<float2*>(C + (size_t)r0       * FF + col) = u0;
            *reinterpret_cast<float2*>(C + (size_t)(r0 + 8) * FF + col) = u1;
        }
    }
}

// ======================================================================
extern "C" void kernel_launch(void* const* d_in, const int* in_sizes, int n_in,
                              void* d_out, int out_size) {
    const float* x    = (const float*)d_in[0];   // [8, 2048, 128]
    const float* adj  = (const float*)d_in[1];   // [8, 2048, 2048]
    const float* w    = (const float*)d_in[2];   // [128, 128]
    const float* bias = (const float*)d_in[3];   // [128]
    float* out = (float*)d_out;                  // [8, 2048, 128]

    cudaFuncSetAttribute(phase1_kernel, cudaFuncAttributeMaxDynamicSharedMemorySize, P1_SMEM);
    cudaFuncSetAttribute(phase2_kernel, cudaFuncAttributeMaxDynamicSharedMemorySize, P2_SMEM);

    phase1_kernel<<<(BB * NN) / P1_BM, 256, P1_SMEM>>>(x, w);
    phase2_kernel<<<dim3(NN / 128, BB), 512, P2_SMEM>>>(adj, bias, out);
}

// round 17
// speedup vs baseline: 3.6860x; 1.2889x over previous
#include <cuda_runtime.h>
#include <cuda_fp16.h>
#include <cstdint>

// GraphConvolution: out[b] = adj[b] @ (x[b] @ W) + bias
// B=8, N=2048, F=128.
// Phase 1: 3-term FP16 mma.sync (fp32-accurate support), stores a SINGLE f16
//          support plane [row][f] (RN-rounded).
// Phase 2: single-term FP16 mma m16n8k16 (f32 acc): adj_f16 x support_f16.
//          512 thr / 16 warps / 32x32 warp tiles / BK=32 / triple buffer /
//          1 sync per chunk (the proven R5/R14 structure, half the MMAs).
//
// Error budget (measured-based): adj f16-RN alone gave rel_err=1.898e-4
// (rounds 5/14). Support f16-RN adds an independent equal term -> ~2.7e-4,
// 3.7x under the 1e-3 threshold. RN is unbiased (round-1's 1.47e-3 failure
// was tf32 *truncation* bias, not random walk).

constexpr int BB = 8;
constexpr int NN = 2048;
constexpr int FF = 128;

__device__ __half g_sup[BB * NN * FF];

// ---------------- common helpers ----------------
__device__ __forceinline__ unsigned s2u(const void* p) {
    return (unsigned)__cvta_generic_to_shared(p);
}
__device__ __forceinline__ void cp16(void* dst, const void* src) {
    asm volatile("cp.async.cg.shared.global [%0], [%1], 16;" :: "r"(s2u(dst)), "l"(src));
}
__device__ __forceinline__ void cpcommit() { asm volatile("cp.async.commit_group;"); }
__device__ __forceinline__ void cpwait1()  { asm volatile("cp.async.wait_group 1;"); }
__device__ __forceinline__ void cpwait0()  { asm volatile("cp.async.wait_group 0;"); }

__device__ __forceinline__ void ldsm_x4(unsigned r[4], unsigned a) {
    asm volatile("ldmatrix.sync.aligned.m8n8.x4.shared.b16 {%0,%1,%2,%3}, [%4];"
                 : "=r"(r[0]), "=r"(r[1]), "=r"(r[2]), "=r"(r[3]) : "r"(a));
}
__device__ __forceinline__ void ldsm_x4_t(unsigned r[4], unsigned a) {
    asm volatile("ldmatrix.sync.aligned.m8n8.x4.trans.shared.b16 {%0,%1,%2,%3}, [%4];"
                 : "=r"(r[0]), "=r"(r[1]), "=r"(r[2]), "=r"(r[3]) : "r"(a));
}
__device__ __forceinline__ void mma_f16(float c[4], const unsigned a[4],
                                        unsigned b0, unsigned b1) {
    asm volatile(
        "mma.sync.aligned.m16n8k16.row.col.f32.f16.f16.f32 "
        "{%0,%1,%2,%3}, {%4,%5,%6,%7}, {%8,%9}, {%0,%1,%2,%3};"
        : "+f"(c[0]), "+f"(c[1]), "+f"(c[2]), "+f"(c[3])
        : "r"(a[0]), "r"(a[1]), "r"(a[2]), "r"(a[3]), "r"(b0), "r"(b1));
}
__device__ __forceinline__ void split_h2(float x, float y, __half2& h, __half2& l) {
    h = __floats2half2_rn(x, y);
    float lx = x - __half2float(__low2half(h));
    float ly = y - __half2float(__high2half(h));
    l = __floats2half2_rn(lx, ly);
}
__device__ __forceinline__ unsigned h2u(__half2 h) {
    return *reinterpret_cast<unsigned*>(&h);
}

// ======================================================================
// Phase 1: support = x @ W (3-term f16 mma), 64 rows/CTA, single chunk
// ======================================================================
constexpr int P1_BM  = 64;
constexpr int LDA_S  = 132;
constexpr int LDB_S  = 136;
constexpr int X_TILE = P1_BM * LDA_S;
constexpr int W_TILE = FF * LDB_S;
constexpr int P1_SMEM = (X_TILE + W_TILE) * 4;   // 103424 B

__global__ __launch_bounds__(256, 1)
void phase1_kernel(const float* __restrict__ x, const float* __restrict__ w)
{
    extern __shared__ float smem1[];
    float* Xs = smem1;
    float* Ws = smem1 + X_TILE;

    const int tid = threadIdx.x;
    const int mtile = blockIdx.x;            // 256 tiles over 16384 rows
    const float* A = x + (size_t)mtile * P1_BM * FF;

    const int warp = tid >> 5, lane = tid & 31;
    const int wm = (warp & 1) * 32;
    const int wn = (warp >> 1) * 32;
    const int g = lane >> 2, t = lane & 3;

#pragma unroll
    for (int i = 0; i < 8; i++) {
        int idx = tid + i * 256;
        int r = idx >> 5, c = idx & 31;
        cp16(Xs + r * LDA_S + c * 4, A + (size_t)r * FF + c * 4);
    }
#pragma unroll
    for (int i = 0; i < 16; i++) {
        int idx = tid + i * 256;
        int r = idx >> 5, c = idx & 31;
        cp16(Ws + r * LDB_S + c * 4, w + (size_t)r * FF + c * 4);
    }
    cpcommit();
    cpwait0();
    __syncthreads();

    float acc[2][4][4];
#pragma unroll
    for (int i = 0; i < 2; i++)
#pragma unroll
        for (int j = 0; j < 4; j++)
#pragma unroll
            for (int k = 0; k < 4; k++) acc[i][j][k] = 0.f;

#pragma unroll
    for (int ks = 0; ks < 8; ks++) {          // K = 128, 16 per step
        unsigned ah[2][4], al[2][4], bh[4][2], bl[4][2];
        const float* Ab = Xs + (wm + g) * LDA_S + ks * 16 + 2 * t;
#pragma unroll
        for (int mf = 0; mf < 2; mf++) {
            const float* p = Ab + mf * 16 * LDA_S;
            float2 v00 = *(const float2*)(p);
            float2 v10 = *(const float2*)(p + 8 * LDA_S);
            float2 v01 = *(const float2*)(p + 8);
            float2 v11 = *(const float2*)(p + 8 * LDA_S + 8);
            __half2 h, l;
            split_h2(v00.x, v00.y, h, l); ah[mf][0] = h2u(h); al[mf][0] = h2u(l);
            split_h2(v10.x, v10.y, h, l); ah[mf][1] = h2u(h); al[mf][1] = h2u(l);
            split_h2(v01.x, v01.y, h, l); ah[mf][2] = h2u(h); al[mf][2] = h2u(l);
            split_h2(v11.x, v11.y, h, l); ah[mf][3] = h2u(h); al[mf][3] = h2u(l);
        }
        const float* Bb = Ws + (ks * 16 + 2 * t) * LDB_S + wn + g;
#pragma unroll
        for (int nf = 0; nf < 4; nf++) {
            float w0 = Bb[nf * 8];
            float w1 = Bb[LDB_S + nf * 8];
            float w2 = Bb[8 * LDB_S + nf * 8];
            float w3 = Bb[9 * LDB_S + nf * 8];
            __half2 h, l;
            split_h2(w0, w1, h, l); bh[nf][0] = h2u(h); bl[nf][0] = h2u(l);
            split_h2(w2, w3, h, l); bh[nf][1] = h2u(h); bl[nf][1] = h2u(l);
        }
#pragma unroll
        for (int mf = 0; mf < 2; mf++)
#pragma unroll
            for (int nf = 0; nf < 4; nf++)
                mma_f16(acc[mf][nf], al[mf], bh[nf][0], bh[nf][1]);
#pragma unroll
        for (int mf = 0; mf < 2; mf++)
#pragma unroll
            for (int nf = 0; nf < 4; nf++)
                mma_f16(acc[mf][nf], ah[mf], bl[nf][0], bl[nf][1]);
#pragma unroll
        for (int mf = 0; mf < 2; mf++)
#pragma unroll
            for (int nf = 0; nf < 4; nf++)
                mma_f16(acc[mf][nf], ah[mf], bh[nf][0], bh[nf][1]);
    }

    // store single f16 plane (RN), [row][f]
    const int rowbase = mtile * P1_BM;
#pragma unroll
    for (int mf = 0; mf < 2; mf++) {
        int r0 = rowbase + wm + mf * 16 + g;
#pragma unroll
        for (int nf = 0; nf < 4; nf++) {
            int col = wn + nf * 8 + 2 * t;
            *(__half2*)(g_sup + (size_t)r0 * FF + col) =
                __floats2half2_rn(acc[mf][nf][0], acc[mf][nf][1]);
            *(__half2*)(g_sup + (size_t)(r0 + 8) * FF + col) =
                __floats2half2_rn(acc[mf][nf][2], acc[mf][nf][3]);
        }
    }
}

// ======================================================================
// Phase 2: out[b] = adj[b] @ support[b] + bias  (single-term f16)
// 512 thr / 16 warps / 32x32 warp tiles / BK=32 / triple buffer / 1 sync
// ======================================================================
constexpr int LDA_H    = 40;                 // halves per A row (32 + 8 pad)
constexpr int A_TILE_B = 128 * LDA_H * 2;    // 10240
constexpr int LDB_B    = 272;                // bytes per B row (256 + 16 pad)
constexpr int B_PLANE  = 32 * LDB_B;         // 8704 (single plane per stage)
constexpr int OFF_BIAS = 0;
constexpr int OFF_A    = 1024;
constexpr int OFF_B    = OFF_A + 3 * A_TILE_B;        // 31744
constexpr int P2_SMEM  = OFF_B + 3 * B_PLANE;         // 57856

__global__ __launch_bounds__(512, 1)
void phase2_kernel(const float* __restrict__ adj, const float* __restrict__ bias,
                   float* __restrict__ out)
{
    extern __shared__ __align__(16) char smem[];
    const unsigned sA = s2u(smem + OFF_A);
    const unsigned sB = s2u(smem + OFF_B);
    const int tid = threadIdx.x, warp = tid >> 5, lane = tid & 31;
    const int mtile = blockIdx.x, b = blockIdx.y;

    const float* A = adj + ((size_t)b * NN + (size_t)mtile * 128) * NN;
    const __half* BH = g_sup + (size_t)b * NN * FF;
    float* C = out + ((size_t)b * NN + (size_t)mtile * 128) * FF;

    if (tid < 128) ((float*)(smem + OFF_BIAS))[tid] = bias[tid];

    // staging roles (512 threads)
    const int ar = tid >> 2, aq = tid & 3;        // A: row 0..127, 8-float quarter
    const int br = tid >> 4, bs = tid & 15;       // B: row 0..31, 16B segment

    // fragment geometry: 16 warps, 32(M) x 32(N) tiles
    const int g = lane >> 2, t = lane & 3;
    const int wm = (warp & 3) * 32;
    const int wn = (warp >> 2) * 32;
    const unsigned aoff = (unsigned)((wm + (lane & 7) + ((lane >> 3) & 1) * 8) * (LDA_H * 2)
                                     + (lane >> 4) * 16);
    const unsigned boff = (unsigned)(((lane & 7) + ((lane >> 3) & 1) * 8) * LDB_B
                                     + (wn + (lane >> 4) * 8) * 2);

    float acc[2][4][4];
#pragma unroll
    for (int i = 0; i < 2; i++)
#pragma unroll
        for (int j = 0; j < 4; j++)
#pragma unroll
            for (int k = 0; k < 4; k++) acc[i][j][k] = 0.f;

    auto ldgA = [&](int kc, float4& v0, float4& v1) {
        const float* p = A + (size_t)ar * NN + kc * 32 + aq * 8;
        v0 = *(const float4*)p;
        v1 = *(const float4*)(p + 4);
    };
    auto stsA = [&](int kc, float4 v0, float4 v1) {
        __half2 p0 = __floats2half2_rn(v0.x, v0.y);
        __half2 p1 = __floats2half2_rn(v0.z, v0.w);
        __half2 p2 = __floats2half2_rn(v1.x, v1.y);
        __half2 p3 = __floats2half2_rn(v1.z, v1.w);
        uint4 u;
        u.x = *(unsigned*)&p0; u.y = *(unsigned*)&p1;
        u.z = *(unsigned*)&p2; u.w = *(unsigned*)&p3;
        *(uint4*)(smem + OFF_A + (kc % 3) * A_TILE_B + ar * (LDA_H * 2) + aq * 16) = u;
    };
    auto cpB = [&](int kc) {
        char* dst = smem + OFF_B + (kc % 3) * B_PLANE + br * LDB_B + bs * 16;
        const __half* sh = BH + (size_t)(kc * 32 + br) * FF + bs * 8;
        cp16(dst, sh);
        cpcommit();
    };

    auto mma_chunk = [&](int j) {
        const unsigned aB = sA + j * A_TILE_B;
        const unsigned bB = sB + j * B_PLANE;
#pragma unroll
        for (int ks = 0; ks < 2; ks++) {
            unsigned af[2][4];
            ldsm_x4(af[0], aB + aoff + ks * 32);
            ldsm_x4(af[1], aB + aoff + 16 * (LDA_H * 2) + ks * 32);
            unsigned bh[2][4];
            const unsigned bks = bB + boff + ks * 16 * LDB_B;
            ldsm_x4_t(bh[0], bks);
            ldsm_x4_t(bh[1], bks + 32);
#pragma unroll
            for (int mf = 0; mf < 2; mf++)
#pragma unroll
                for (int np = 0; np < 2; np++)
#pragma unroll
                    for (int p = 0; p < 2; p++)
                        mma_f16(acc[mf][np * 2 + p], af[mf],
                                bh[np][p * 2], bh[np][p * 2 + 1]);
        }
    };

    // prologue: chunks 0 and 1
    {
        float4 v0, v1;
        ldgA(0, v0, v1); stsA(0, v0, v1); cpB(0);
        ldgA(1, v0, v1); stsA(1, v0, v1); cpB(1);
    }

    for (int kc = 0; kc < 64; kc++) {
        float4 v0, v1;
        const bool pre = (kc + 2 < 64);
        if (pre) ldgA(kc + 2, v0, v1);           // overlap LDG with wait+MMA
        if (kc < 63) cpwait1(); else cpwait0();
        __syncthreads();
        mma_chunk(kc % 3);
        if (pre) {
            stsA(kc + 2, v0, v1);
            cpB(kc + 2);
        }
    }

    // epilogue
    const float* bsm = (const float*)(smem + OFF_BIAS);
#pragma unroll
    for (int mf = 0; mf < 2; mf++) {
        int r0 = wm + mf * 16 + g;
#pragma unroll
        for (int nf = 0; nf < 4; nf++) {
            int col = wn + nf * 8 + 2 * t;
            float2 bz = *reinterpret_cast<const float2*>(bsm + col);
            float2 u0 = make_float2(acc[mf][nf][0] + bz.x, acc[mf][nf][1] + bz.y);
            float2 u1 = make_float2(acc[mf][nf][2] + bz.x, acc[mf][nf][3] + bz.y);
            *reinterpret_cast<float2*>(C + (size_t)r0       * FF + col) = u0;
            *reinterpret_cast<float2*>(C + (size_t)(r0 + 8) * FF + col) = u1;
        }
    }
}

// ======================================================================
extern "C" void kernel_launch(void* const* d_in, const int* in_sizes, int n_in,
                              void* d_out, int out_size) {
    const float* x    = (const float*)d_in[0];   // [8, 2048, 128]
    const float* adj  = (const float*)d_in[1];   // [8, 2048, 2048]
    const float* w    = (const float*)d_in[2];   // [128, 128]
    const float* bias = (const float*)d_in[3];   // [128]
    float* out = (float*)d_out;                  // [8, 2048, 128]

    cudaFuncSetAttribute(phase1_kernel, cudaFuncAttributeMaxDynamicSharedMemorySize, P1_SMEM);
    cudaFuncSetAttribute(phase2_kernel, cudaFuncAttributeMaxDynamicSharedMemorySize, P2_SMEM);

    phase1_kernel<<<(BB * NN) / P1_BM, 256, P1_SMEM>>>(x, w);
    phase2_kernel<<<dim3(NN / 128, BB), 512, P2_SMEM>>>(adj, bias, out);
}